// round 10
// baseline (speedup 1.0000x reference)
#include <cuda_runtime.h>
#include <cuda_bf16.h>
#include <math.h>

// Problem constants
#define HH   1024
#define BB   64
#define SS   512
#define NIN  128
#define NOUT 128

// Recurrence config: 128 persistent CTAs = JCH j-chunks x KSP k-splits
#define NCTA 128
#define JCH  16     // j chunks of 64
#define KSP  8      // k splits of 128
#define JW   64     // j per CTA
#define KW   128    // k per CTA
#define RT   256    // threads per CTA
#define HSTRIDE 130 // hs_d row stride in u64 (EVEN: 16B-aligned rows, offset banks)

typedef unsigned long long u64;

// Scratch (static device memory — no runtime allocation)
__device__ float    g_buf0[(size_t)BB * SS * HH];    // 128 MB: xp0, then xp1
__device__ float    g_buf1[(size_t)BB * SS * HH];    // 128 MB: h0seq, then h1seq
__device__ float    g_part[(size_t)KSP * BB * HH];   // 2 MB split-K partials [s][b][j]
__device__ unsigned g_barA[SS * JCH];                // partials-ready, per (t, jc)
__device__ unsigned g_barB[SS];                      // h-ready, global per t

// ---------------------------------------------------------------------------
// Packed fp32x2 helpers (SASS FFMA2 — only reachable via explicit PTX)
// ---------------------------------------------------------------------------
__device__ __forceinline__ u64 dupf2(float x) {
    u64 r;
    asm("mov.b64 %0, {%1, %1};" : "=l"(r) : "f"(x));
    return r;
}
__device__ __forceinline__ u64 packf2(float lo, float hi) {
    u64 r;
    asm("mov.b64 %0, {%1, %2};" : "=l"(r) : "f"(lo), "f"(hi));
    return r;
}
__device__ __forceinline__ void ffma2(u64& d, u64 a, u64 b) {
    asm("fma.rn.f32x2 %0, %1, %2, %0;" : "+l"(d) : "l"(a), "l"(b));
}
__device__ __forceinline__ u64 addf2(u64 a, u64 b) {
    u64 r;
    asm("add.rn.f32x2 %0, %1, %2;" : "=l"(r) : "l"(a), "l"(b));
    return r;
}

// ---------------------------------------------------------------------------
// Barrier counter reset (launched before each recurrence kernel)
// ---------------------------------------------------------------------------
__global__ void zero_bar_kernel() {
    int i = blockIdx.x * blockDim.x + threadIdx.x;
    if (i < SS * JCH) g_barA[i] = 0u;
    if (i < SS) g_barB[i] = 0u;
}

// ---------------------------------------------------------------------------
// Spin barrier among `target` co-resident CTAs (R3-proven structure)
// ---------------------------------------------------------------------------
__device__ __forceinline__ void bar_sync(unsigned* ctr, unsigned target) {
    __threadfence();          // release
    __syncthreads();
    if (threadIdx.x == 0) {
        unsigned prev = atomicAdd(ctr, 1u);
        if (prev + 1u < target) {
            volatile unsigned* p = (volatile unsigned*)ctr;
            while (*p < target) { __nanosleep(40); }
        }
        __threadfence();      // acquire
    }
    __syncthreads();
}

// ---------------------------------------------------------------------------
// Persistent recurrence kernel:
//   for t in [0, S): hseq[:,t,:] = tanh(xp[:,t,:] + hseq[:,t-1,:] @ Whh^T)
// CTA (jc, ks): partial over k-segment ks (128 wide) for j-chunk jc (64 wide).
// Sync per step: barA[t][jc] (8-CTA group: partials ready) +
//                barB[t]     (global: h(t) fully written).
// Inner loop: SMEM-duplicated h + natural w pairs => pure LDS.128 + FFMA2.
// ---------------------------------------------------------------------------
__global__ void __launch_bounds__(RT, 1) rnn_kernel(const float* __restrict__ xp,
                                                    float* __restrict__ hseq,
                                                    const float* __restrict__ Whh) {
    extern __shared__ char smraw[];
    float* ws  = reinterpret_cast<float*>(smraw);                 // [KW][JW] 32 KB
    u64*   hsd = reinterpret_cast<u64*>(smraw + KW * JW * 4);     // [BB][HSTRIDE] 65 KB

    const int cta = blockIdx.x;
    const int jc  = cta >> 3;            // 0..15
    const int ks  = cta & (KSP - 1);     // 0..7
    const int J0  = jc * JW;
    const int K0  = ks * KW;
    const int tid = threadIdx.x;

    // Load weight chunk once: Whh[J0+j][K0+k] -> ws[k][j]
    {
        int j = tid >> 2;                // 0..63
        int q = tid & 3;                 // 0..3 (32-k strips)
        const float4* src = reinterpret_cast<const float4*>(
            Whh + (size_t)(J0 + j) * HH + K0 + q * 32);
#pragma unroll
        for (int r = 0; r < 8; ++r) {
            float4 v = src[r];
            int k = q * 32 + r * 4;
            ws[(size_t)(k + 0) * JW + j] = v.x;
            ws[(size_t)(k + 1) * JW + j] = v.y;
            ws[(size_t)(k + 2) * JW + j] = v.z;
            ws[(size_t)(k + 3) * JW + j] = v.w;
        }
    }
    __syncthreads();

    // Compute-phase thread tile: 2 batches x 8 j
    const int tx = tid & 7;              // j group
    const int ty = tid >> 3;             // b pair (0..31)
    const int b0 = ty * 2;
    const int j0 = tx * 8;

    // Reduce slice: within own jc group (64 b x 64 j), j fastest, coalesced
    const int idx = ks * 512 + tid * 2;  // 0..4095 within group
    const int rb  = idx >> 6;            // 0..63
    const int rj  = J0 + (idx & 63);     // even

    for (int t = 0; t < SS; ++t) {
        // Prefetch xp pair for the reduce phase
        float2 xv = __ldg(reinterpret_cast<const float2*>(
            xp + ((size_t)rb * SS + t) * HH + rj));

        if (t > 0) {
            // Stage h chunk (coalesced): rows of hseq[.][t-1][K0..K0+128)
            // linear float4 index i2: row = i2>>5, col4 = i2&31
#pragma unroll
            for (int r = 0; r < 8; ++r) {
                int i2  = r * 256 + tid;
                int row = i2 >> 5;
                int c4  = i2 & 31;
                float4 v = __ldcg(reinterpret_cast<const float4*>(
                    hseq + ((size_t)row * SS + (t - 1)) * HH + K0 + c4 * 4));
                ulonglong2 p0, p1;
                p0.x = dupf2(v.x); p0.y = dupf2(v.y);
                p1.x = dupf2(v.z); p1.y = dupf2(v.w);
                u64* dst = &hsd[(size_t)row * HSTRIDE + c4 * 4];
                *reinterpret_cast<ulonglong2*>(dst)     = p0;
                *reinterpret_cast<ulonglong2*>(dst + 2) = p1;
            }
            __syncthreads();

            // acc[b][p]: batch offset b (2), j-pair p (4)
            u64 acc[2][4];
#pragma unroll
            for (int b = 0; b < 2; ++b)
#pragma unroll
                for (int p = 0; p < 4; ++p) acc[b][p] = 0ull;

            const u64* hrow0 = &hsd[(size_t)b0 * HSTRIDE];
            const u64* hrow1 = &hsd[(size_t)(b0 + 1) * HSTRIDE];

#pragma unroll 8
            for (int k = 0; k < KW; k += 2) {
                ulonglong2 hA = *reinterpret_cast<const ulonglong2*>(hrow0 + k);
                ulonglong2 hB = *reinterpret_cast<const ulonglong2*>(hrow1 + k);
                {   // k
                    ulonglong2 w0 = *reinterpret_cast<const ulonglong2*>(&ws[(size_t)k * JW + j0]);
                    ulonglong2 w1 = *reinterpret_cast<const ulonglong2*>(&ws[(size_t)k * JW + j0 + 4]);
                    ffma2(acc[0][0], hA.x, w0.x); ffma2(acc[0][1], hA.x, w0.y);
                    ffma2(acc[0][2], hA.x, w1.x); ffma2(acc[0][3], hA.x, w1.y);
                    ffma2(acc[1][0], hB.x, w0.x); ffma2(acc[1][1], hB.x, w0.y);
                    ffma2(acc[1][2], hB.x, w1.x); ffma2(acc[1][3], hB.x, w1.y);
                }
                {   // k+1
                    ulonglong2 w0 = *reinterpret_cast<const ulonglong2*>(&ws[(size_t)(k + 1) * JW + j0]);
                    ulonglong2 w1 = *reinterpret_cast<const ulonglong2*>(&ws[(size_t)(k + 1) * JW + j0 + 4]);
                    ffma2(acc[0][0], hA.y, w0.x); ffma2(acc[0][1], hA.y, w0.y);
                    ffma2(acc[0][2], hA.y, w1.x); ffma2(acc[0][3], hA.y, w1.y);
                    ffma2(acc[1][0], hB.y, w0.x); ffma2(acc[1][1], hB.y, w0.y);
                    ffma2(acc[1][2], hB.y, w1.x); ffma2(acc[1][3], hB.y, w1.y);
                }
            }

            // Write split-K partials: g_part[ks][b][j], 2x16B per b row
            float* pb0 = g_part + (size_t)ks * BB * HH + (size_t)b0 * HH + J0 + j0;
            ulonglong2 s0, s1;
            s0.x = acc[0][0]; s0.y = acc[0][1];
            s1.x = acc[0][2]; s1.y = acc[0][3];
            *reinterpret_cast<ulonglong2*>(pb0)     = s0;
            *reinterpret_cast<ulonglong2*>(pb0 + 4) = s1;
            s0.x = acc[1][0]; s0.y = acc[1][1];
            s1.x = acc[1][2]; s1.y = acc[1][3];
            *reinterpret_cast<ulonglong2*>(pb0 + HH)     = s0;
            *reinterpret_cast<ulonglong2*>(pb0 + HH + 4) = s1;
        }

        // Group barrier: all 8 partials of group jc ready
        bar_sync(&g_barA[t * JCH + jc], KSP);

        // Reduce + tanh for this CTA's slice (own jc group, coalesced)
        {
            float v0 = xv.x, v1 = xv.y;
            if (t > 0) {
                const float* pb = g_part + (size_t)rb * HH + rj;
#pragma unroll
                for (int s = 0; s < KSP; ++s) {
                    float2 p = __ldcg(reinterpret_cast<const float2*>(
                        pb + (size_t)s * BB * HH));
                    v0 += p.x;
                    v1 += p.y;
                }
            }
            float2 hv;
            hv.x = tanhf(v0);
            hv.y = tanhf(v1);
            *reinterpret_cast<float2*>(hseq + ((size_t)rb * SS + t) * HH + rj) = hv;
        }

        // Global barrier: h(t) fully written before anyone stages it
        bar_sync(&g_barB[t], NCTA);
    }
}

// ---------------------------------------------------------------------------
// Tiled fp32 GEMM with bias:  C[M,N] = A[M,K] @ B[N,K]^T + bias1 + bias2
// BM=BN=128, BK=16, 256 threads, 8x8 register tiles, FFMA2 inner product.
// ---------------------------------------------------------------------------
__global__ void __launch_bounds__(256) gemm_bias_kernel(const float* __restrict__ A,
                                                        const float* __restrict__ Bm,
                                                        const float* __restrict__ bias1,
                                                        const float* __restrict__ bias2,
                                                        float* __restrict__ C,
                                                        int K, int N) {
    constexpr int BM = 128, BN = 128, BK = 16;
    __shared__ float As[BK][BM + 4];
    __shared__ float Bs[BK][BN + 4];

    const int tid   = threadIdx.x;
    const int mBase = blockIdx.y * BM;
    const int nBase = blockIdx.x * BN;
    const int tx = tid & 15;
    const int ty = tid >> 4;
    const int lr = tid >> 2;
    const int lc = (tid & 3) * 4;

    u64 acc[8][4];
#pragma unroll
    for (int i = 0; i < 8; ++i)
#pragma unroll
        for (int p = 0; p < 4; ++p) acc[i][p] = 0ull;

    const int NT = K / BK;
    for (int kt = 0; kt < NT; ++kt) {
#pragma unroll
        for (int h = 0; h < 2; ++h) {
            int r = lr + h * 64;
            float4 va = *reinterpret_cast<const float4*>(
                A + (size_t)(mBase + r) * K + kt * BK + lc);
            As[lc + 0][r] = va.x; As[lc + 1][r] = va.y;
            As[lc + 2][r] = va.z; As[lc + 3][r] = va.w;
            float4 vb = *reinterpret_cast<const float4*>(
                Bm + (size_t)(nBase + r) * K + kt * BK + lc);
            Bs[lc + 0][r] = vb.x; Bs[lc + 1][r] = vb.y;
            Bs[lc + 2][r] = vb.z; Bs[lc + 3][r] = vb.w;
        }
        __syncthreads();

#pragma unroll
        for (int k = 0; k < BK; ++k) {
            float4 a0 = *reinterpret_cast<const float4*>(&As[k][ty * 4]);
            float4 a1 = *reinterpret_cast<const float4*>(&As[k][64 + ty * 4]);
            ulonglong2 bA = *reinterpret_cast<const ulonglong2*>(&Bs[k][tx * 4]);
            ulonglong2 bB = *reinterpret_cast<const ulonglong2*>(&Bs[k][64 + tx * 4]);
            u64 ad[8];
            ad[0] = dupf2(a0.x); ad[1] = dupf2(a0.y);
            ad[2] = dupf2(a0.z); ad[3] = dupf2(a0.w);
            ad[4] = dupf2(a1.x); ad[5] = dupf2(a1.y);
            ad[6] = dupf2(a1.z); ad[7] = dupf2(a1.w);
#pragma unroll
            for (int i = 0; i < 8; ++i) {
                ffma2(acc[i][0], ad[i], bA.x);
                ffma2(acc[i][1], ad[i], bA.y);
                ffma2(acc[i][2], ad[i], bB.x);
                ffma2(acc[i][3], ad[i], bB.y);
            }
        }
        __syncthreads();
    }

    u64 bb[4];
#pragma unroll
    for (int p = 0; p < 4; ++p) {
        int n = nBase + ((p < 2) ? (tx * 4 + p * 2) : (64 + tx * 4 + (p - 2) * 2));
        float v0 = bias1[n];
        float v1 = bias1[n + 1];
        if (bias2) { v0 += bias2[n]; v1 += bias2[n + 1]; }
        bb[p] = packf2(v0, v1);
    }
#pragma unroll
    for (int i = 0; i < 8; ++i) {
        int m = mBase + ((i < 4) ? (ty * 4 + i) : (64 + ty * 4 + (i - 4)));
        ulonglong2 oa, ob;
        oa.x = addf2(acc[i][0], bb[0]); oa.y = addf2(acc[i][1], bb[1]);
        ob.x = addf2(acc[i][2], bb[2]); ob.y = addf2(acc[i][3], bb[3]);
        *reinterpret_cast<ulonglong2*>(C + (size_t)m * N + nBase + tx * 4) = oa;
        *reinterpret_cast<ulonglong2*>(C + (size_t)m * N + nBase + 64 + tx * 4) = ob;
    }
}

// ---------------------------------------------------------------------------
// Final FC: out[b,n] = hseq[b, S-1, :] . Wfc[n, :] + bfc[n]
// ---------------------------------------------------------------------------
__global__ void __launch_bounds__(128) fc_kernel(const float* __restrict__ hseq,
                                                 const float* __restrict__ Wfc,
                                                 const float* __restrict__ bfc,
                                                 float* __restrict__ out) {
    __shared__ float hsh[HH];
    const int b = blockIdx.x;
    const float* hrow = hseq + ((size_t)b * SS + (SS - 1)) * HH;
    for (int k = threadIdx.x; k < HH; k += 128) hsh[k] = hrow[k];
    __syncthreads();

    const int n = threadIdx.x;
    float acc = bfc[n];
    const float* w = Wfc + (size_t)n * HH;
#pragma unroll 8
    for (int k = 0; k < HH; ++k) acc += hsh[k] * __ldg(w + k);
    out[b * NOUT + n] = acc;
}

// ---------------------------------------------------------------------------
// Entry point
// ---------------------------------------------------------------------------
extern "C" void kernel_launch(void* const* d_in, const int* in_sizes, int n_in,
                              void* d_out, int out_size) {
    const float* x    = (const float*)d_in[0];
    const float* Wih0 = (const float*)d_in[1];
    const float* bih0 = (const float*)d_in[2];
    const float* Whh0 = (const float*)d_in[3];
    const float* bhh0 = (const float*)d_in[4];
    const float* Wih1 = (const float*)d_in[5];
    const float* bih1 = (const float*)d_in[6];
    const float* Whh1 = (const float*)d_in[7];
    const float* bhh1 = (const float*)d_in[8];
    const float* Wfc  = (const float*)d_in[9];
    const float* bfc  = (const float*)d_in[10];
    float* out = (float*)d_out;

    float *buf0 = nullptr, *buf1 = nullptr;
    cudaGetSymbolAddress((void**)&buf0, g_buf0);
    cudaGetSymbolAddress((void**)&buf1, g_buf1);

    const int rnn_smem = KW * JW * 4 + BB * HSTRIDE * 8;  // 32 KB + 65 KB = 97 KB
    cudaFuncSetAttribute(rnn_kernel, cudaFuncAttributeMaxDynamicSharedMemorySize,
                         rnn_smem);

    dim3 gproj(HH / 128, (BB * SS) / 128);  // (8, 256)

    // Phase A: xp0 = x @ Wih0^T + bih0 + bhh0
    gemm_bias_kernel<<<gproj, 256>>>(x, Wih0, bih0, bhh0, buf0, NIN, HH);

    // Phase B: layer-0 recurrence -> h0seq in buf1
    zero_bar_kernel<<<34, 256>>>();
    rnn_kernel<<<NCTA, RT, rnn_smem>>>(buf0, buf1, Whh0);

    // Phase C: xp1 = h0seq @ Wih1^T + bih1 + bhh1 (overwrites buf0)
    gemm_bias_kernel<<<gproj, 256>>>(buf1, Wih1, bih1, bhh1, buf0, HH, HH);

    // Phase D: layer-1 recurrence -> h1seq in buf1
    zero_bar_kernel<<<34, 256>>>();
    rnn_kernel<<<NCTA, RT, rnn_smem>>>(buf0, buf1, Whh1);

    // Phase E: out = h1seq[:, S-1, :] @ Wfc^T + bfc
    fc_kernel<<<BB, 128>>>(buf1, Wfc, bfc, out);
}

// round 12
// speedup vs baseline: 1.8274x; 1.8274x over previous
#include <cuda_runtime.h>
#include <cuda_bf16.h>
#include <math.h>

// Problem constants
#define HH   1024
#define BB   64
#define SS   512
#define NIN  128
#define NOUT 128

// Recurrence config (R3-proven tiling): 128 CTAs = JCH j-chunks x KSP k-splits
#define NCTA 128
#define JCH  4      // j chunks of 256
#define KSP  32     // k splits of 32
#define JW   256    // j per CTA
#define KW   32     // k per CTA
#define RT   256    // threads per CTA
#define NMS  (SS + 2)   // 514 macro-steps (layer-1 lags by 2)

typedef unsigned long long u64;

// Scratch (static device memory — no runtime allocation)
__device__ float    g_xp0[(size_t)BB * SS * HH];   // 128 MB: layer-0 input proj
__device__ float    g_h0 [(size_t)BB * SS * HH];   // 128 MB: layer-0 hidden seq
__device__ float    g_h1 [(size_t)BB * SS * HH];   // 128 MB: layer-1 hidden seq
__device__ float    g_p0 [(size_t)KSP * BB * HH];  // 8 MB split-K partials (layer 0)
__device__ float    g_p1 [(size_t)KSP * BB * HH];  // 8 MB split-K partials (layer 1)
__device__ float    g_b1s[HH];                     // bih1 + bhh1
__device__ unsigned g_bar[2 * NMS];                // per-macro-step barrier counters

// ---------------------------------------------------------------------------
// Packed fp32x2 helpers (SASS FFMA2 — only reachable via explicit PTX)
// ---------------------------------------------------------------------------
__device__ __forceinline__ u64 dupf2(float x) {
    u64 r;
    asm("mov.b64 %0, {%1, %1};" : "=l"(r) : "f"(x));
    return r;
}
__device__ __forceinline__ u64 packf2(float lo, float hi) {
    u64 r;
    asm("mov.b64 %0, {%1, %2};" : "=l"(r) : "f"(lo), "f"(hi));
    return r;
}
__device__ __forceinline__ void ffma2(u64& d, u64 a, u64 b) {
    asm("fma.rn.f32x2 %0, %1, %2, %0;" : "+l"(d) : "l"(a), "l"(b));
}
__device__ __forceinline__ u64 addf2(u64 a, u64 b) {
    u64 r;
    asm("add.rn.f32x2 %0, %1, %2;" : "=l"(r) : "l"(a), "l"(b));
    return r;
}

// ---------------------------------------------------------------------------
// Setup: zero barrier counters, precompute b1s = bih1 + bhh1
// ---------------------------------------------------------------------------
__global__ void setup_kernel(const float* __restrict__ bih1,
                             const float* __restrict__ bhh1) {
    int i = blockIdx.x * blockDim.x + threadIdx.x;
    if (i < 2 * NMS) g_bar[i] = 0u;
    if (i < HH) g_b1s[i] = bih1[i] + bhh1[i];
}

// ---------------------------------------------------------------------------
// Grid-wide spin barrier among NCTA co-resident CTAs (R3-proven structure)
// ---------------------------------------------------------------------------
__device__ __forceinline__ void grid_barrier(int ev) {
    __threadfence();          // release
    __syncthreads();
    if (threadIdx.x == 0) {
        unsigned prev = atomicAdd(&g_bar[ev], 1u);
        if (prev + 1u < (unsigned)NCTA) {
            volatile unsigned* p = (volatile unsigned*)&g_bar[ev];
            while (*p < (unsigned)NCTA) { __nanosleep(40); }
        }
        __threadfence();      // acquire
    }
    __syncthreads();
}

// ---------------------------------------------------------------------------
// Stage one [64 b x 32 k] slice of a hidden-seq buffer into SMEM, duplicated:
// dst[k*BB + b] = dupf2(seq[b][t][K0+k]).  (u64 units: one dup per batch.)
// ---------------------------------------------------------------------------
__device__ __forceinline__ void stage_dup(const float* __restrict__ seq, int t,
                                          u64* dst, int sbb, int sq, int K0) {
    const float4* src = reinterpret_cast<const float4*>(
        seq + ((size_t)sbb * SS + t) * HH + K0 + sq * 8);
    float4 v0 = __ldcg(src);
    float4 v1 = __ldcg(src + 1);
    int k = sq * 8;
    dst[(size_t)(k + 0) * BB + sbb] = dupf2(v0.x);
    dst[(size_t)(k + 1) * BB + sbb] = dupf2(v0.y);
    dst[(size_t)(k + 2) * BB + sbb] = dupf2(v0.z);
    dst[(size_t)(k + 3) * BB + sbb] = dupf2(v0.w);
    dst[(size_t)(k + 4) * BB + sbb] = dupf2(v1.x);
    dst[(size_t)(k + 5) * BB + sbb] = dupf2(v1.y);
    dst[(size_t)(k + 6) * BB + sbb] = dupf2(v1.z);
    dst[(size_t)(k + 7) * BB + sbb] = dupf2(v1.w);
}

// ---------------------------------------------------------------------------
// One 32-k chunk GEMM: acc[8b][4 j-pairs] += hbuf(dup) x wsX. Pure FFMA2.
// h loads are warp-uniform (broadcast); w loads are R3's conflict-free split.
// ---------------------------------------------------------------------------
__device__ __forceinline__ void gemm_chunk(const float* wsX, const u64* hbuf,
                                           u64 (&acc)[8][4], int b0, int jA, int jB) {
#pragma unroll 4
    for (int k = 0; k < KW; ++k) {
        const u64* hrow = hbuf + (size_t)k * BB + b0;   // dup(b0..b0+7)
        ulonglong2 h01 = *reinterpret_cast<const ulonglong2*>(hrow);
        ulonglong2 h23 = *reinterpret_cast<const ulonglong2*>(hrow + 2);
        ulonglong2 h45 = *reinterpret_cast<const ulonglong2*>(hrow + 4);
        ulonglong2 h67 = *reinterpret_cast<const ulonglong2*>(hrow + 6);
        ulonglong2 wA = *reinterpret_cast<const ulonglong2*>(wsX + (size_t)k * JW + jA);
        ulonglong2 wB = *reinterpret_cast<const ulonglong2*>(wsX + (size_t)k * JW + jB);
        u64 hd[8] = {h01.x, h01.y, h23.x, h23.y, h45.x, h45.y, h67.x, h67.y};
        u64 wv[4] = {wA.x, wA.y, wB.x, wB.y};
#pragma unroll
        for (int i = 0; i < 8; ++i) {
            ffma2(acc[i][0], hd[i], wv[0]);
            ffma2(acc[i][1], hd[i], wv[1]);
            ffma2(acc[i][2], hd[i], wv[2]);
            ffma2(acc[i][3], hd[i], wv[3]);
        }
    }
}

// Write split-K partials: part[ks][b][j], 16B j-pair stores (R3 pattern)
__device__ __forceinline__ void store_partials(float* part, int ks, int b0,
                                               int jA, int jB, int J0,
                                               const u64 (&acc)[8][4]) {
    float* pbase = part + (size_t)ks * BB * HH + (size_t)b0 * HH + J0;
#pragma unroll
    for (int i = 0; i < 8; ++i) {
        ulonglong2 pa; pa.x = acc[i][0]; pa.y = acc[i][1];
        ulonglong2 pb; pb.x = acc[i][2]; pb.y = acc[i][3];
        *reinterpret_cast<ulonglong2*>(pbase + (size_t)i * HH + jA) = pa;
        *reinterpret_cast<ulonglong2*>(pbase + (size_t)i * HH + jB) = pb;
    }
}

// ---------------------------------------------------------------------------
// Fused 2-layer pipelined recurrence. Macro-step u (0..513):
//   h0(u)   = tanh(xp0(u)   + h0(u-1) @ Whh0^T)               [u <= 511]
//   h1(u-2) = tanh(b1s + h0(u-2) @ Wih1^T + h1(u-3) @ Whh1^T) [u >= 2]
// CTA (jc, ks): 256-j chunk jc, 32-k segment ks of each GEMM.
// h0(u-2) is the previous macro-step's staged h0 tile (SMEM ping-pong).
// ---------------------------------------------------------------------------
__global__ void __launch_bounds__(RT, 1) fused_rnn_kernel(
        const float* __restrict__ Whh0,
        const float* __restrict__ WihI,
        const float* __restrict__ Whh1) {
    extern __shared__ char smraw[];
    float* ws0 = reinterpret_cast<float*>(smraw);                  // 32 KB
    float* wsI = reinterpret_cast<float*>(smraw + 32768);          // 32 KB
    float* ws1 = reinterpret_cast<float*>(smraw + 65536);          // 32 KB
    u64*   hA0 = reinterpret_cast<u64*>(smraw + 98304);            // 16 KB
    u64*   hA1 = reinterpret_cast<u64*>(smraw + 114688);           // 16 KB
    u64*   hC  = reinterpret_cast<u64*>(smraw + 131072);           // 16 KB

    const int cta = blockIdx.x;
    const int jc  = cta & (JCH - 1);     // 0..3
    const int ks  = cta >> 2;            // 0..31
    const int J0  = jc * JW;
    const int K0  = ks * KW;
    const int tid = threadIdx.x;

    // Load the three weight chunks: W[J0+j][K0+k] -> ws[k][j]
    {
        const float4* s0 = reinterpret_cast<const float4*>(Whh0 + (size_t)(J0 + tid) * HH + K0);
        const float4* sI = reinterpret_cast<const float4*>(WihI + (size_t)(J0 + tid) * HH + K0);
        const float4* s1 = reinterpret_cast<const float4*>(Whh1 + (size_t)(J0 + tid) * HH + K0);
#pragma unroll
        for (int q = 0; q < 8; ++q) {
            float4 v = s0[q];
            ws0[(size_t)(q * 4 + 0) * JW + tid] = v.x;
            ws0[(size_t)(q * 4 + 1) * JW + tid] = v.y;
            ws0[(size_t)(q * 4 + 2) * JW + tid] = v.z;
            ws0[(size_t)(q * 4 + 3) * JW + tid] = v.w;
            v = sI[q];
            wsI[(size_t)(q * 4 + 0) * JW + tid] = v.x;
            wsI[(size_t)(q * 4 + 1) * JW + tid] = v.y;
            wsI[(size_t)(q * 4 + 2) * JW + tid] = v.z;
            wsI[(size_t)(q * 4 + 3) * JW + tid] = v.w;
            v = s1[q];
            ws1[(size_t)(q * 4 + 0) * JW + tid] = v.x;
            ws1[(size_t)(q * 4 + 1) * JW + tid] = v.y;
            ws1[(size_t)(q * 4 + 2) * JW + tid] = v.z;
            ws1[(size_t)(q * 4 + 3) * JW + tid] = v.w;
        }
    }
    __syncthreads();

    // Compute-phase thread tile: 8 batches x 8 j (4+4 split), R3-proven maps
    const int tx = tid & 31;
    const int ty = tid >> 5;
    const int b0 = ty * 8;
    const int jA = tx * 4;
    const int jB = 128 + tx * 4;

    // Reduce slice: fully coalesced, j fastest over whole [b][j] plane
    const int e0 = cta * 512 + tid * 2;  // 0..65535
    const int rb = e0 >> 10;             // 0..63
    const int rj = e0 & 1023;            // even

    // Staging map
    const int sbb = tid >> 2;            // 0..63 batch row
    const int sq  = tid & 3;             // 0..3 (8-k strips)

    // Layer-1 bias pair (constant across steps)
    const float2 bv = __ldg(reinterpret_cast<const float2*>(g_b1s + rj));

    for (int u = 0; u < NMS; ++u) {
        // Prefetch xp0 pair for reduce0
        float2 xv = make_float2(0.f, 0.f);
        if (u <= SS - 1)
            xv = __ldg(reinterpret_cast<const float2*>(
                g_xp0 + ((size_t)rb * SS + u) * HH + rj));

        // Stage: A = h0(u-1) into ping-pong; C = h1(u-3)
        u64* hAcur = (u & 1) ? hA1 : hA0;
        u64* hAprv = (u & 1) ? hA0 : hA1;   // holds h0(u-2)
        if (u >= 1 && u <= SS) stage_dup(g_h0, u - 1, hAcur, sbb, sq, K0);
        if (u >= 3)            stage_dup(g_h1, u - 3, hC,    sbb, sq, K0);
        __syncthreads();

        // Partials for layer 0: h0(u-1) @ Whh0 chunk
        if (u >= 1 && u <= SS - 1) {
            u64 acc[8][4];
#pragma unroll
            for (int i = 0; i < 8; ++i)
#pragma unroll
                for (int p = 0; p < 4; ++p) acc[i][p] = 0ull;
            gemm_chunk(ws0, hAcur, acc, b0, jA, jB);
            store_partials(g_p0, ks, b0, jA, jB, J0, acc);
        }

        // Partials for layer 1: h0(u-2) @ Wih1 chunk (+ h1(u-3) @ Whh1 chunk)
        if (u >= 2) {
            u64 acc[8][4];
#pragma unroll
            for (int i = 0; i < 8; ++i)
#pragma unroll
                for (int p = 0; p < 4; ++p) acc[i][p] = 0ull;
            gemm_chunk(wsI, hAprv, acc, b0, jA, jB);
            if (u >= 3) gemm_chunk(ws1, hC, acc, b0, jA, jB);
            store_partials(g_p1, ks, b0, jA, jB, J0, acc);
        }

        grid_barrier(2 * u);   // all partials of macro-step u ready

        // Reduce 0: h0(u) = tanh(xp0(u) + sum partials0)
        if (u <= SS - 1) {
            float v0 = xv.x, v1 = xv.y;
            if (u >= 1) {
                const float* pb = g_p0 + (size_t)rb * HH + rj;
#pragma unroll
                for (int s = 0; s < KSP; ++s) {
                    float2 p = __ldcg(reinterpret_cast<const float2*>(
                        pb + (size_t)s * BB * HH));
                    v0 += p.x;
                    v1 += p.y;
                }
            }
            float2 hv;
            hv.x = tanhf(v0);
            hv.y = tanhf(v1);
            *reinterpret_cast<float2*>(g_h0 + ((size_t)rb * SS + u) * HH + rj) = hv;
        }

        // Reduce 1: h1(u-2) = tanh(b1s + sum partials1)
        if (u >= 2) {
            float v0 = bv.x, v1 = bv.y;
            const float* pb = g_p1 + (size_t)rb * HH + rj;
#pragma unroll
            for (int s = 0; s < KSP; ++s) {
                float2 p = __ldcg(reinterpret_cast<const float2*>(
                    pb + (size_t)s * BB * HH));
                v0 += p.x;
                v1 += p.y;
            }
            float2 hv;
            hv.x = tanhf(v0);
            hv.y = tanhf(v1);
            *reinterpret_cast<float2*>(g_h1 + ((size_t)rb * SS + (u - 2)) * HH + rj) = hv;
        }

        grid_barrier(2 * u + 1);  // outputs of macro-step u fully written
    }
}

// ---------------------------------------------------------------------------
// Tiled fp32 GEMM with bias:  C[M,N] = A[M,K] @ B[N,K]^T + bias1 + bias2
// (phase A only: xp0 = x @ Wih0^T + bih0 + bhh0)
// ---------------------------------------------------------------------------
__global__ void __launch_bounds__(256) gemm_bias_kernel(const float* __restrict__ A,
                                                        const float* __restrict__ Bm,
                                                        const float* __restrict__ bias1,
                                                        const float* __restrict__ bias2,
                                                        float* __restrict__ C,
                                                        int K, int N) {
    constexpr int BM = 128, BN = 128, BK = 16;
    __shared__ float As[BK][BM + 4];
    __shared__ float Bs[BK][BN + 4];

    const int tid   = threadIdx.x;
    const int mBase = blockIdx.y * BM;
    const int nBase = blockIdx.x * BN;
    const int tx = tid & 15;
    const int ty = tid >> 4;
    const int lr = tid >> 2;
    const int lc = (tid & 3) * 4;

    u64 acc[8][4];
#pragma unroll
    for (int i = 0; i < 8; ++i)
#pragma unroll
        for (int p = 0; p < 4; ++p) acc[i][p] = 0ull;

    const int NT = K / BK;
    for (int kt = 0; kt < NT; ++kt) {
#pragma unroll
        for (int h = 0; h < 2; ++h) {
            int r = lr + h * 64;
            float4 va = *reinterpret_cast<const float4*>(
                A + (size_t)(mBase + r) * K + kt * BK + lc);
            As[lc + 0][r] = va.x; As[lc + 1][r] = va.y;
            As[lc + 2][r] = va.z; As[lc + 3][r] = va.w;
            float4 vb = *reinterpret_cast<const float4*>(
                Bm + (size_t)(nBase + r) * K + kt * BK + lc);
            Bs[lc + 0][r] = vb.x; Bs[lc + 1][r] = vb.y;
            Bs[lc + 2][r] = vb.z; Bs[lc + 3][r] = vb.w;
        }
        __syncthreads();

#pragma unroll
        for (int k = 0; k < BK; ++k) {
            float4 a0 = *reinterpret_cast<const float4*>(&As[k][ty * 4]);
            float4 a1 = *reinterpret_cast<const float4*>(&As[k][64 + ty * 4]);
            ulonglong2 bA = *reinterpret_cast<const ulonglong2*>(&Bs[k][tx * 4]);
            ulonglong2 bB = *reinterpret_cast<const ulonglong2*>(&Bs[k][64 + tx * 4]);
            u64 ad[8];
            ad[0] = dupf2(a0.x); ad[1] = dupf2(a0.y);
            ad[2] = dupf2(a0.z); ad[3] = dupf2(a0.w);
            ad[4] = dupf2(a1.x); ad[5] = dupf2(a1.y);
            ad[6] = dupf2(a1.z); ad[7] = dupf2(a1.w);
#pragma unroll
            for (int i = 0; i < 8; ++i) {
                ffma2(acc[i][0], ad[i], bA.x);
                ffma2(acc[i][1], ad[i], bA.y);
                ffma2(acc[i][2], ad[i], bB.x);
                ffma2(acc[i][3], ad[i], bB.y);
            }
        }
        __syncthreads();
    }

    u64 bb[4];
#pragma unroll
    for (int p = 0; p < 4; ++p) {
        int n = nBase + ((p < 2) ? (tx * 4 + p * 2) : (64 + tx * 4 + (p - 2) * 2));
        float v0 = bias1[n];
        float v1 = bias1[n + 1];
        if (bias2) { v0 += bias2[n]; v1 += bias2[n + 1]; }
        bb[p] = packf2(v0, v1);
    }
#pragma unroll
    for (int i = 0; i < 8; ++i) {
        int m = mBase + ((i < 4) ? (ty * 4 + i) : (64 + ty * 4 + (i - 4)));
        ulonglong2 oa, ob;
        oa.x = addf2(acc[i][0], bb[0]); oa.y = addf2(acc[i][1], bb[1]);
        ob.x = addf2(acc[i][2], bb[2]); ob.y = addf2(acc[i][3], bb[3]);
        *reinterpret_cast<ulonglong2*>(C + (size_t)m * N + nBase + tx * 4) = oa;
        *reinterpret_cast<ulonglong2*>(C + (size_t)m * N + nBase + 64 + tx * 4) = ob;
    }
}

// ---------------------------------------------------------------------------
// Final FC: out[b,n] = h1[b, S-1, :] . Wfc[n, :] + bfc[n]
// ---------------------------------------------------------------------------
__global__ void __launch_bounds__(128) fc_kernel(const float* __restrict__ Wfc,
                                                 const float* __restrict__ bfc,
                                                 float* __restrict__ out) {
    __shared__ float hsh[HH];
    const int b = blockIdx.x;
    const float* hrow = g_h1 + ((size_t)b * SS + (SS - 1)) * HH;
    for (int k = threadIdx.x; k < HH; k += 128) hsh[k] = hrow[k];
    __syncthreads();

    const int n = threadIdx.x;
    float acc = bfc[n];
    const float* w = Wfc + (size_t)n * HH;
#pragma unroll 8
    for (int k = 0; k < HH; ++k) acc += hsh[k] * __ldg(w + k);
    out[b * NOUT + n] = acc;
}

// ---------------------------------------------------------------------------
// Entry point
// ---------------------------------------------------------------------------
extern "C" void kernel_launch(void* const* d_in, const int* in_sizes, int n_in,
                              void* d_out, int out_size) {
    const float* x    = (const float*)d_in[0];
    const float* Wih0 = (const float*)d_in[1];
    const float* bih0 = (const float*)d_in[2];
    const float* Whh0 = (const float*)d_in[3];
    const float* bhh0 = (const float*)d_in[4];
    const float* Wih1 = (const float*)d_in[5];
    const float* bih1 = (const float*)d_in[6];
    const float* Whh1 = (const float*)d_in[7];
    const float* bhh1 = (const float*)d_in[8];
    const float* Wfc  = (const float*)d_in[9];
    const float* bfc  = (const float*)d_in[10];
    float* out = (float*)d_out;

    float* xp0 = nullptr;
    cudaGetSymbolAddress((void**)&xp0, g_xp0);

    const int rnn_smem = 147456;  // 3x32KB weights + 3x16KB dup-stage = 144 KB
    cudaFuncSetAttribute(fused_rnn_kernel,
                         cudaFuncAttributeMaxDynamicSharedMemorySize, rnn_smem);

    dim3 gproj(HH / 128, (BB * SS) / 128);  // (8, 256)

    // Phase A: xp0 = x @ Wih0^T + bih0 + bhh0
    gemm_bias_kernel<<<gproj, 256>>>(x, Wih0, bih0, bhh0, xp0, NIN, HH);

    // Setup: barrier counters + layer-1 bias sum
    setup_kernel<<<5, 256>>>(bih1, bhh1);

    // Fused pipelined 2-layer recurrence
    fused_rnn_kernel<<<NCTA, RT, rnn_smem>>>(Whh0, Wih1, Whh1);

    // FC: out = h1[:, S-1, :] @ Wfc^T + bfc
    fc_kernel<<<BB, 128>>>(Wfc, bfc, out);
}

// round 13
// speedup vs baseline: 1.9840x; 1.0857x over previous
#include <cuda_runtime.h>
#include <cuda_bf16.h>
#include <math.h>

// Problem constants
#define HH   1024
#define BB   64
#define SS   512
#define NIN  128
#define NOUT 128

// Recurrence config (R3-proven tiling): 128 CTAs = JCH j-chunks x KSP k-splits
#define NCTA 128
#define JCH  4      // j chunks of 256
#define KSP  32     // k splits of 32
#define JW   256    // j per CTA
#define KW   32     // k per CTA
#define RT   256    // threads per CTA
#define NMS  (SS + 2)   // 514 macro-steps (layer-1 lags by 2)

typedef unsigned long long u64;

// Scratch (static device memory — no runtime allocation)
__device__ float    g_xp0[(size_t)BB * SS * HH];   // 128 MB: layer-0 input proj
__device__ float    g_h0 [(size_t)BB * SS * HH];   // 128 MB: layer-0 hidden seq
__device__ float    g_h1 [(size_t)BB * SS * HH];   // 128 MB: layer-1 hidden seq
__device__ float    g_p0 [(size_t)KSP * BB * HH];  // 8 MB split-K partials (layer 0)
__device__ float    g_p1 [(size_t)KSP * BB * HH];  // 8 MB split-K partials (layer 1)
__device__ float    g_b1s[HH];                     // bih1 + bhh1
__device__ unsigned g_bar[2 * NMS];                // per-macro-step barrier counters

// ---------------------------------------------------------------------------
// Packed fp32x2 helpers (SASS FFMA2 — only reachable via explicit PTX)
// ---------------------------------------------------------------------------
__device__ __forceinline__ u64 dupf2(float x) {
    u64 r;
    asm("mov.b64 %0, {%1, %1};" : "=l"(r) : "f"(x));
    return r;
}
__device__ __forceinline__ u64 packf2(float lo, float hi) {
    u64 r;
    asm("mov.b64 %0, {%1, %2};" : "=l"(r) : "f"(lo), "f"(hi));
    return r;
}
__device__ __forceinline__ void ffma2(u64& d, u64 a, u64 b) {
    asm("fma.rn.f32x2 %0, %1, %2, %0;" : "+l"(d) : "l"(a), "l"(b));
}
__device__ __forceinline__ u64 addf2(u64 a, u64 b) {
    u64 r;
    asm("add.rn.f32x2 %0, %1, %2;" : "=l"(r) : "l"(a), "l"(b));
    return r;
}

// ---------------------------------------------------------------------------
// Setup: zero barrier counters, precompute b1s = bih1 + bhh1
// ---------------------------------------------------------------------------
__global__ void setup_kernel(const float* __restrict__ bih1,
                             const float* __restrict__ bhh1) {
    int i = blockIdx.x * blockDim.x + threadIdx.x;
    if (i < 2 * NMS) g_bar[i] = 0u;
    if (i < HH) g_b1s[i] = bih1[i] + bhh1[i];
}

// ---------------------------------------------------------------------------
// Grid-wide barrier, single-leader protocol (cg::grid_sync pattern):
// bar.sync gives CTA-scope hb; leader's acq_rel atomic is CUMULATIVE at gpu
// scope (publishes ALL CTA threads' prior stores); waiters acquire the
// counter. No per-thread GPU membars.
// ---------------------------------------------------------------------------
__device__ __forceinline__ void grid_barrier(int ev) {
    __syncthreads();
    if (threadIdx.x == 0) {
        unsigned* ctr = &g_bar[ev];
        unsigned prev;
        asm volatile("atom.acq_rel.gpu.global.add.u32 %0, [%1], 1;"
                     : "=r"(prev) : "l"(ctr) : "memory");
        if (prev + 1u < (unsigned)NCTA) {
            unsigned v;
            do {
                asm volatile("ld.acquire.gpu.global.u32 %0, [%1];"
                             : "=r"(v) : "l"(ctr) : "memory");
                if (v >= (unsigned)NCTA) break;
                __nanosleep(32);
            } while (true);
        }
    }
    __syncthreads();
}

// ---------------------------------------------------------------------------
// Stage one [64 b x 32 k] slice of a hidden-seq buffer into SMEM, duplicated:
// dst[k*BB + b] = dupf2(seq[b][t][K0+k]).  (u64 units: one dup per batch.)
// ---------------------------------------------------------------------------
__device__ __forceinline__ void stage_dup(const float* __restrict__ seq, int t,
                                          u64* dst, int sbb, int sq, int K0) {
    const float4* src = reinterpret_cast<const float4*>(
        seq + ((size_t)sbb * SS + t) * HH + K0 + sq * 8);
    float4 v0 = __ldcg(src);
    float4 v1 = __ldcg(src + 1);
    int k = sq * 8;
    dst[(size_t)(k + 0) * BB + sbb] = dupf2(v0.x);
    dst[(size_t)(k + 1) * BB + sbb] = dupf2(v0.y);
    dst[(size_t)(k + 2) * BB + sbb] = dupf2(v0.z);
    dst[(size_t)(k + 3) * BB + sbb] = dupf2(v0.w);
    dst[(size_t)(k + 4) * BB + sbb] = dupf2(v1.x);
    dst[(size_t)(k + 5) * BB + sbb] = dupf2(v1.y);
    dst[(size_t)(k + 6) * BB + sbb] = dupf2(v1.z);
    dst[(size_t)(k + 7) * BB + sbb] = dupf2(v1.w);
}

// ---------------------------------------------------------------------------
// One 32-k chunk GEMM: acc[8b][4 j-pairs] += hbuf(dup) x wsX. Pure FFMA2.
// h loads are warp-uniform (broadcast); w loads are R3's conflict-free split.
// ---------------------------------------------------------------------------
__device__ __forceinline__ void gemm_chunk(const float* wsX, const u64* hbuf,
                                           u64 (&acc)[8][4], int b0, int jA, int jB) {
#pragma unroll 4
    for (int k = 0; k < KW; ++k) {
        const u64* hrow = hbuf + (size_t)k * BB + b0;   // dup(b0..b0+7)
        ulonglong2 h01 = *reinterpret_cast<const ulonglong2*>(hrow);
        ulonglong2 h23 = *reinterpret_cast<const ulonglong2*>(hrow + 2);
        ulonglong2 h45 = *reinterpret_cast<const ulonglong2*>(hrow + 4);
        ulonglong2 h67 = *reinterpret_cast<const ulonglong2*>(hrow + 6);
        ulonglong2 wA = *reinterpret_cast<const ulonglong2*>(wsX + (size_t)k * JW + jA);
        ulonglong2 wB = *reinterpret_cast<const ulonglong2*>(wsX + (size_t)k * JW + jB);
        u64 hd[8] = {h01.x, h01.y, h23.x, h23.y, h45.x, h45.y, h67.x, h67.y};
        u64 wv[4] = {wA.x, wA.y, wB.x, wB.y};
#pragma unroll
        for (int i = 0; i < 8; ++i) {
            ffma2(acc[i][0], hd[i], wv[0]);
            ffma2(acc[i][1], hd[i], wv[1]);
            ffma2(acc[i][2], hd[i], wv[2]);
            ffma2(acc[i][3], hd[i], wv[3]);
        }
    }
}

// Write split-K partials: part[ks][b][j], 16B j-pair stores (R3 pattern)
__device__ __forceinline__ void store_partials(float* part, int ks, int b0,
                                               int jA, int jB, int J0,
                                               const u64 (&acc)[8][4]) {
    float* pbase = part + (size_t)ks * BB * HH + (size_t)b0 * HH + J0;
#pragma unroll
    for (int i = 0; i < 8; ++i) {
        ulonglong2 pa; pa.x = acc[i][0]; pa.y = acc[i][1];
        ulonglong2 pb; pb.x = acc[i][2]; pb.y = acc[i][3];
        *reinterpret_cast<ulonglong2*>(pbase + (size_t)i * HH + jA) = pa;
        *reinterpret_cast<ulonglong2*>(pbase + (size_t)i * HH + jB) = pb;
    }
}

// ---------------------------------------------------------------------------
// Fused 2-layer pipelined recurrence. Macro-step u (0..513):
//   h0(u)   = tanh(xp0(u)   + h0(u-1) @ Whh0^T)               [u <= 511]
//   h1(u-2) = tanh(b1s + h0(u-2) @ Wih1^T + h1(u-3) @ Whh1^T) [u >= 2]
// CTA (jc, ks): 256-j chunk jc, 32-k segment ks of each GEMM.
// h0(u-2) is the previous macro-step's staged h0 tile (SMEM ping-pong).
// ---------------------------------------------------------------------------
__global__ void __launch_bounds__(RT, 1) fused_rnn_kernel(
        const float* __restrict__ Whh0,
        const float* __restrict__ WihI,
        const float* __restrict__ Whh1) {
    extern __shared__ char smraw[];
    float* ws0 = reinterpret_cast<float*>(smraw);                  // 32 KB
    float* wsI = reinterpret_cast<float*>(smraw + 32768);          // 32 KB
    float* ws1 = reinterpret_cast<float*>(smraw + 65536);          // 32 KB
    u64*   hA0 = reinterpret_cast<u64*>(smraw + 98304);            // 16 KB
    u64*   hA1 = reinterpret_cast<u64*>(smraw + 114688);           // 16 KB
    u64*   hC  = reinterpret_cast<u64*>(smraw + 131072);           // 16 KB

    const int cta = blockIdx.x;
    const int jc  = cta & (JCH - 1);     // 0..3
    const int ks  = cta >> 2;            // 0..31
    const int J0  = jc * JW;
    const int K0  = ks * KW;
    const int tid = threadIdx.x;

    // Load the three weight chunks: W[J0+j][K0+k] -> ws[k][j]
    {
        const float4* s0 = reinterpret_cast<const float4*>(Whh0 + (size_t)(J0 + tid) * HH + K0);
        const float4* sI = reinterpret_cast<const float4*>(WihI + (size_t)(J0 + tid) * HH + K0);
        const float4* s1 = reinterpret_cast<const float4*>(Whh1 + (size_t)(J0 + tid) * HH + K0);
#pragma unroll
        for (int q = 0; q < 8; ++q) {
            float4 v = s0[q];
            ws0[(size_t)(q * 4 + 0) * JW + tid] = v.x;
            ws0[(size_t)(q * 4 + 1) * JW + tid] = v.y;
            ws0[(size_t)(q * 4 + 2) * JW + tid] = v.z;
            ws0[(size_t)(q * 4 + 3) * JW + tid] = v.w;
            v = sI[q];
            wsI[(size_t)(q * 4 + 0) * JW + tid] = v.x;
            wsI[(size_t)(q * 4 + 1) * JW + tid] = v.y;
            wsI[(size_t)(q * 4 + 2) * JW + tid] = v.z;
            wsI[(size_t)(q * 4 + 3) * JW + tid] = v.w;
            v = s1[q];
            ws1[(size_t)(q * 4 + 0) * JW + tid] = v.x;
            ws1[(size_t)(q * 4 + 1) * JW + tid] = v.y;
            ws1[(size_t)(q * 4 + 2) * JW + tid] = v.z;
            ws1[(size_t)(q * 4 + 3) * JW + tid] = v.w;
        }
    }
    __syncthreads();

    // Compute-phase thread tile: 8 batches x 8 j (4+4 split), R3-proven maps
    const int tx = tid & 31;
    const int ty = tid >> 5;
    const int b0 = ty * 8;
    const int jA = tx * 4;
    const int jB = 128 + tx * 4;

    // Reduce slice: fully coalesced, j fastest over whole [b][j] plane
    const int e0 = cta * 512 + tid * 2;  // 0..65535
    const int rb = e0 >> 10;             // 0..63
    const int rj = e0 & 1023;            // even

    // Staging map
    const int sbb = tid >> 2;            // 0..63 batch row
    const int sq  = tid & 3;             // 0..3 (8-k strips)

    // Layer-1 bias pair (constant across steps)
    const float2 bv = __ldg(reinterpret_cast<const float2*>(g_b1s + rj));

    for (int u = 0; u < NMS; ++u) {
        // Prefetch xp0 pair for reduce0
        float2 xv = make_float2(0.f, 0.f);
        if (u <= SS - 1)
            xv = __ldg(reinterpret_cast<const float2*>(
                g_xp0 + ((size_t)rb * SS + u) * HH + rj));

        // Stage: A = h0(u-1) into ping-pong; C = h1(u-3)
        u64* hAcur = (u & 1) ? hA1 : hA0;
        u64* hAprv = (u & 1) ? hA0 : hA1;   // holds h0(u-2)
        if (u >= 1 && u <= SS) stage_dup(g_h0, u - 1, hAcur, sbb, sq, K0);
        if (u >= 3)            stage_dup(g_h1, u - 3, hC,    sbb, sq, K0);
        __syncthreads();

        // Partials for layer 0: h0(u-1) @ Whh0 chunk
        if (u >= 1 && u <= SS - 1) {
            u64 acc[8][4];
#pragma unroll
            for (int i = 0; i < 8; ++i)
#pragma unroll
                for (int p = 0; p < 4; ++p) acc[i][p] = 0ull;
            gemm_chunk(ws0, hAcur, acc, b0, jA, jB);
            store_partials(g_p0, ks, b0, jA, jB, J0, acc);
        }

        // Partials for layer 1: h0(u-2) @ Wih1 chunk (+ h1(u-3) @ Whh1 chunk)
        if (u >= 2) {
            u64 acc[8][4];
#pragma unroll
            for (int i = 0; i < 8; ++i)
#pragma unroll
                for (int p = 0; p < 4; ++p) acc[i][p] = 0ull;
            gemm_chunk(wsI, hAprv, acc, b0, jA, jB);
            if (u >= 3) gemm_chunk(ws1, hC, acc, b0, jA, jB);
            store_partials(g_p1, ks, b0, jA, jB, J0, acc);
        }

        grid_barrier(2 * u);   // all partials of macro-step u ready

        // Reduce 0: h0(u) = tanh(xp0(u) + sum partials0)
        if (u <= SS - 1) {
            float v0 = xv.x, v1 = xv.y;
            if (u >= 1) {
                const float* pb = g_p0 + (size_t)rb * HH + rj;
#pragma unroll
                for (int s = 0; s < KSP; ++s) {
                    float2 p = __ldcg(reinterpret_cast<const float2*>(
                        pb + (size_t)s * BB * HH));
                    v0 += p.x;
                    v1 += p.y;
                }
            }
            float2 hv;
            hv.x = tanhf(v0);
            hv.y = tanhf(v1);
            *reinterpret_cast<float2*>(g_h0 + ((size_t)rb * SS + u) * HH + rj) = hv;
        }

        // Reduce 1: h1(u-2) = tanh(b1s + sum partials1)
        if (u >= 2) {
            float v0 = bv.x, v1 = bv.y;
            const float* pb = g_p1 + (size_t)rb * HH + rj;
#pragma unroll
            for (int s = 0; s < KSP; ++s) {
                float2 p = __ldcg(reinterpret_cast<const float2*>(
                    pb + (size_t)s * BB * HH));
                v0 += p.x;
                v1 += p.y;
            }
            float2 hv;
            hv.x = tanhf(v0);
            hv.y = tanhf(v1);
            *reinterpret_cast<float2*>(g_h1 + ((size_t)rb * SS + (u - 2)) * HH + rj) = hv;
        }

        grid_barrier(2 * u + 1);  // outputs of macro-step u fully written
    }
}

// ---------------------------------------------------------------------------
// Tiled fp32 GEMM with bias:  C[M,N] = A[M,K] @ B[N,K]^T + bias1 + bias2
// (phase A only: xp0 = x @ Wih0^T + bih0 + bhh0)
// ---------------------------------------------------------------------------
__global__ void __launch_bounds__(256) gemm_bias_kernel(const float* __restrict__ A,
                                                        const float* __restrict__ Bm,
                                                        const float* __restrict__ bias1,
                                                        const float* __restrict__ bias2,
                                                        float* __restrict__ C,
                                                        int K, int N) {
    constexpr int BM = 128, BN = 128, BK = 16;
    __shared__ float As[BK][BM + 4];
    __shared__ float Bs[BK][BN + 4];

    const int tid   = threadIdx.x;
    const int mBase = blockIdx.y * BM;
    const int nBase = blockIdx.x * BN;
    const int tx = tid & 15;
    const int ty = tid >> 4;
    const int lr = tid >> 2;
    const int lc = (tid & 3) * 4;

    u64 acc[8][4];
#pragma unroll
    for (int i = 0; i < 8; ++i)
#pragma unroll
        for (int p = 0; p < 4; ++p) acc[i][p] = 0ull;

    const int NT = K / BK;
    for (int kt = 0; kt < NT; ++kt) {
#pragma unroll
        for (int h = 0; h < 2; ++h) {
            int r = lr + h * 64;
            float4 va = *reinterpret_cast<const float4*>(
                A + (size_t)(mBase + r) * K + kt * BK + lc);
            As[lc + 0][r] = va.x; As[lc + 1][r] = va.y;
            As[lc + 2][r] = va.z; As[lc + 3][r] = va.w;
            float4 vb = *reinterpret_cast<const float4*>(
                Bm + (size_t)(nBase + r) * K + kt * BK + lc);
            Bs[lc + 0][r] = vb.x; Bs[lc + 1][r] = vb.y;
            Bs[lc + 2][r] = vb.z; Bs[lc + 3][r] = vb.w;
        }
        __syncthreads();

#pragma unroll
        for (int k = 0; k < BK; ++k) {
            float4 a0 = *reinterpret_cast<const float4*>(&As[k][ty * 4]);
            float4 a1 = *reinterpret_cast<const float4*>(&As[k][64 + ty * 4]);
            ulonglong2 bA = *reinterpret_cast<const ulonglong2*>(&Bs[k][tx * 4]);
            ulonglong2 bB = *reinterpret_cast<const ulonglong2*>(&Bs[k][64 + tx * 4]);
            u64 ad[8];
            ad[0] = dupf2(a0.x); ad[1] = dupf2(a0.y);
            ad[2] = dupf2(a0.z); ad[3] = dupf2(a0.w);
            ad[4] = dupf2(a1.x); ad[5] = dupf2(a1.y);
            ad[6] = dupf2(a1.z); ad[7] = dupf2(a1.w);
#pragma unroll
            for (int i = 0; i < 8; ++i) {
                ffma2(acc[i][0], ad[i], bA.x);
                ffma2(acc[i][1], ad[i], bA.y);
                ffma2(acc[i][2], ad[i], bB.x);
                ffma2(acc[i][3], ad[i], bB.y);
            }
        }
        __syncthreads();
    }

    u64 bb[4];
#pragma unroll
    for (int p = 0; p < 4; ++p) {
        int n = nBase + ((p < 2) ? (tx * 4 + p * 2) : (64 + tx * 4 + (p - 2) * 2));
        float v0 = bias1[n];
        float v1 = bias1[n + 1];
        if (bias2) { v0 += bias2[n]; v1 += bias2[n + 1]; }
        bb[p] = packf2(v0, v1);
    }
#pragma unroll
    for (int i = 0; i < 8; ++i) {
        int m = mBase + ((i < 4) ? (ty * 4 + i) : (64 + ty * 4 + (i - 4)));
        ulonglong2 oa, ob;
        oa.x = addf2(acc[i][0], bb[0]); oa.y = addf2(acc[i][1], bb[1]);
        ob.x = addf2(acc[i][2], bb[2]); ob.y = addf2(acc[i][3], bb[3]);
        *reinterpret_cast<ulonglong2*>(C + (size_t)m * N + nBase + tx * 4) = oa;
        *reinterpret_cast<ulonglong2*>(C + (size_t)m * N + nBase + 64 + tx * 4) = ob;
    }
}

// ---------------------------------------------------------------------------
// Final FC: out[b,n] = h1[b, S-1, :] . Wfc[n, :] + bfc[n]
// Warp-per-row, lane-strided float4 loads (coalesced), shfl reduction.
// ---------------------------------------------------------------------------
__global__ void __launch_bounds__(256) fc_kernel(const float* __restrict__ Wfc,
                                                 const float* __restrict__ bfc,
                                                 float* __restrict__ out) {
    __shared__ float hsh[HH];
    const int b = blockIdx.x;
    const float* hrow = g_h1 + ((size_t)b * SS + (SS - 1)) * HH;
    for (int k = threadIdx.x; k < HH; k += 256) hsh[k] = hrow[k];
    __syncthreads();

    const int warp = threadIdx.x >> 5;
    const int lane = threadIdx.x & 31;
    const float4* hv4 = reinterpret_cast<const float4*>(hsh);

    for (int n = warp; n < NOUT; n += 8) {
        const float4* w = reinterpret_cast<const float4*>(
            Wfc + (size_t)n * HH) + lane;
        float acc = 0.f;
#pragma unroll
        for (int i = 0; i < 8; ++i) {
            float4 wv = __ldg(w + i * 32);
            float4 hv = hv4[lane + i * 32];
            acc += wv.x * hv.x + wv.y * hv.y + wv.z * hv.z + wv.w * hv.w;
        }
#pragma unroll
        for (int off = 16; off; off >>= 1)
            acc += __shfl_down_sync(0xFFFFFFFFu, acc, off);
        if (lane == 0) out[b * NOUT + n] = acc + bfc[n];
    }
}

// ---------------------------------------------------------------------------
// Entry point
// ---------------------------------------------------------------------------
extern "C" void kernel_launch(void* const* d_in, const int* in_sizes, int n_in,
                              void* d_out, int out_size) {
    const float* x    = (const float*)d_in[0];
    const float* Wih0 = (const float*)d_in[1];
    const float* bih0 = (const float*)d_in[2];
    const float* Whh0 = (const float*)d_in[3];
    const float* bhh0 = (const float*)d_in[4];
    const float* Wih1 = (const float*)d_in[5];
    const float* bih1 = (const float*)d_in[6];
    const float* Whh1 = (const float*)d_in[7];
    const float* bhh1 = (const float*)d_in[8];
    const float* Wfc  = (const float*)d_in[9];
    const float* bfc  = (const float*)d_in[10];
    float* out = (float*)d_out;

    float* xp0 = nullptr;
    cudaGetSymbolAddress((void**)&xp0, g_xp0);

    const int rnn_smem = 147456;  // 3x32KB weights + 3x16KB dup-stage = 144 KB
    cudaFuncSetAttribute(fused_rnn_kernel,
                         cudaFuncAttributeMaxDynamicSharedMemorySize, rnn_smem);

    dim3 gproj(HH / 128, (BB * SS) / 128);  // (8, 256)

    // Phase A: xp0 = x @ Wih0^T + bih0 + bhh0
    gemm_bias_kernel<<<gproj, 256>>>(x, Wih0, bih0, bhh0, xp0, NIN, HH);

    // Setup: barrier counters + layer-1 bias sum
    setup_kernel<<<5, 256>>>(bih1, bhh1);

    // Fused pipelined 2-layer recurrence
    fused_rnn_kernel<<<NCTA, RT, rnn_smem>>>(Whh0, Wih1, Whh1);

    // FC: out = h1[:, S-1, :] @ Wfc^T + bfc
    fc_kernel<<<BB, 256>>>(Wfc, bfc, out);
}